// round 15
// baseline (speedup 1.0000x reference)
#include <cuda_runtime.h>
#include <math.h>

#define NCLS 21

// ---------------- f32x2 packed helpers ----------------
__device__ __forceinline__ unsigned long long f2_fma(unsigned long long a,
                                                     unsigned long long b,
                                                     unsigned long long c) {
  unsigned long long d;
  asm("fma.rn.f32x2 %0, %1, %2, %3;" : "=l"(d) : "l"(a), "l"(b), "l"(c));
  return d;
}
__device__ __forceinline__ unsigned long long f2_add(unsigned long long a,
                                                     unsigned long long b) {
  unsigned long long d;
  asm("add.rn.f32x2 %0, %1, %2;" : "=l"(d) : "l"(a), "l"(b));
  return d;
}
__device__ __forceinline__ unsigned long long f2_bcast(float x) {
  unsigned long long d;
  asm("mov.b64 %0, {%1, %1};" : "=l"(d) : "f"(x));
  return d;
}
__device__ __forceinline__ void f2_unpack(unsigned long long v, float& lo,
                                          float& hi) {
  asm("mov.b64 {%0, %1}, %2;" : "=f"(lo), "=f"(hi) : "l"(v));
}
#define F2_NEG1 0xBF800000BF800000ULL  // (-1.0f, -1.0f)

// ---------------- cp.async helpers ----------------
__device__ __forceinline__ void cp16(unsigned dst, const void* src,
                                     int srcsize) {
  asm volatile("cp.async.cg.shared.global [%0], [%1], 16, %2;" ::"r"(dst),
               "l"(src), "r"(srcsize));
}
__device__ __forceinline__ void cp_commit() {
  asm volatile("cp.async.commit_group;");
}
__device__ __forceinline__ void cp_wait_all() {
  asm volatile("cp.async.wait_group 0;");
}

// ---------------- scratch ----------------
__device__ float g_h1[64 * 256 * 256];
__device__ float g_h2[128 * 128 * 128];
__device__ float g_h3[256 * 64 * 64];
__device__ float g_h4[256 * 32 * 32];
__device__ float g_expart[4 * 256 * 32 * 32];
__device__ float g_part[8 * 25 * 1024];
__device__ float g_locs[1024 * 4];
__device__ float g_confs[1024 * NCLS];
__device__ int g_labels[1024];
__device__ int g_order[1024];
__device__ float4 g_sbox[1024];
__device__ float g_sscore[1024];
__device__ unsigned g_validmask[32];
__device__ unsigned g_sup[1024 * 32];
__device__ unsigned g_keepmask[32];

// ================= conv1 (R11-proven, unchanged) ==============================
__global__ void __launch_bounds__(256) k_conv1(const float* __restrict__ x,
                                               const float* __restrict__ w,
                                               const float* __restrict__ b) {
  constexpr int IN_H = 34, ROWP = 68, IN_W4 = 17;
  constexpr int CHE4 = IN_H * IN_W4;
  constexpr int ELEMS4 = 3 * CHE4;
  constexpr int LD4 = 7;
  __shared__ __align__(16) float s_in[3 * IN_H * ROWP];
  __shared__ __align__(16) float s_w[3 * 9 * 8];

  const int t = threadIdx.x;
  const int tx = t & 15, ty = t >> 4;
  const int ow0 = blockIdx.x * 32, oh0 = blockIdx.y * 16;
  const int co0 = blockIdx.z * 8;

  if (t < 216) {
    int co = t / 27, rem = t - co * 27;
    s_w[rem * 8 + co] = w[(size_t)(co0 + co) * 27 + rem];
  }
#pragma unroll
  for (int i = 0; i < LD4; ++i) {
    int idx = t + i * 256;
    if (idx < ELEMS4) {
      int ch = idx / CHE4, rem = idx - ch * CHE4;
      int r = rem / IN_W4, c4 = rem - r * IN_W4;
      int ih = oh0 * 2 + r, iw = ow0 * 2 + c4 * 4;
      float4 v = make_float4(0.f, 0.f, 0.f, 0.f);
      if (ih < 512 && iw < 512)
        v = *(const float4*)(x + (size_t)ch * 512 * 512 + ih * 512 + iw);
      *(float4*)&s_in[(ch * IN_H + r) * ROWP + c4 * 4] = v;
    }
  }
  __syncthreads();

  unsigned long long acc2[8], cmp2[8];
#pragma unroll
  for (int i = 0; i < 8; ++i) { acc2[i] = 0ull; cmp2[i] = 0ull; }

#pragma unroll
  for (int ch = 0; ch < 3; ++ch) {
    unsigned long long wsA[4] = {0ull, 0ull, 0ull, 0ull};
    unsigned long long wsB[4] = {0ull, 0ull, 0ull, 0ull};
#pragma unroll
    for (int kh = 0; kh < 3; ++kh) {
      const int rbase = (ch * IN_H + ty * 2 + kh) * ROWP + tx * 4;
      float4 xr = *(const float4*)&s_in[rbase];
      float x4v = s_in[rbase + 4];
      float x0s[3] = {xr.x, xr.y, xr.z};
      float x1s[3] = {xr.z, xr.w, x4v};
#pragma unroll
      for (int kw = 0; kw < 3; ++kw) {
        unsigned long long x0 = f2_bcast(x0s[kw]);
        unsigned long long x1 = f2_bcast(x1s[kw]);
        const ulonglong2* wp = (const ulonglong2*)&s_w[(ch * 9 + kh * 3 + kw) * 8];
        ulonglong2 wa = wp[0], wb = wp[1];
        wsA[0] = f2_fma(x0, wa.x, wsA[0]);
        wsA[1] = f2_fma(x0, wa.y, wsA[1]);
        wsA[2] = f2_fma(x0, wb.x, wsA[2]);
        wsA[3] = f2_fma(x0, wb.y, wsA[3]);
        wsB[0] = f2_fma(x1, wa.x, wsB[0]);
        wsB[1] = f2_fma(x1, wa.y, wsB[1]);
        wsB[2] = f2_fma(x1, wb.x, wsB[2]);
        wsB[3] = f2_fma(x1, wb.y, wsB[3]);
      }
    }
#pragma unroll
    for (int i = 0; i < 4; ++i) {
      unsigned long long y = f2_fma(cmp2[i], F2_NEG1, wsA[i]);
      unsigned long long tt = f2_add(acc2[i], y);
      unsigned long long t2 = f2_fma(acc2[i], F2_NEG1, tt);
      cmp2[i] = f2_fma(y, F2_NEG1, t2);
      acc2[i] = tt;
    }
#pragma unroll
    for (int i = 0; i < 4; ++i) {
      unsigned long long y = f2_fma(cmp2[4 + i], F2_NEG1, wsB[i]);
      unsigned long long tt = f2_add(acc2[4 + i], y);
      unsigned long long t2 = f2_fma(acc2[4 + i], F2_NEG1, tt);
      cmp2[4 + i] = f2_fma(y, F2_NEG1, t2);
      acc2[4 + i] = tt;
    }
  }

  const int oh = oh0 + ty;
  const int ow = ow0 + tx * 2;
#pragma unroll
  for (int px = 0; px < 2; ++px) {
#pragma unroll
    for (int i = 0; i < 4; ++i) {
      float lo, hi;
      f2_unpack(acc2[px * 4 + i], lo, hi);
      lo = fmaxf(lo + b[co0 + 2 * i], 0.f);
      hi = fmaxf(hi + b[co0 + 2 * i + 1], 0.f);
      g_h1[(size_t)(co0 + 2 * i) * 65536 + (size_t)oh * 256 + ow + px] = lo;
      g_h1[(size_t)(co0 + 2 * i + 1) * 65536 + (size_t)oh * 256 + ow + px] = hi;
    }
  }
}

// ============= wide conv (exact R13-proven version) ==========================
template <int CINFULL, int NCHUNKS, bool FINAL>
__device__ __forceinline__ void conv_wide(const float* __restrict__ in,
                                          const float* __restrict__ wgt,
                                          const float* __restrict__ bias,
                                          float* __restrict__ out, int Hin,
                                          int Win, int Hout, int Wout,
                                          int c_begin, int co0) {
  constexpr int WCH = 32, NCH = 4;
  constexpr int IN_H = 34, ROWP = 68;
  constexpr int IN_W4 = 17;
  constexpr int CHE4 = IN_H * IN_W4;
  constexpr int ELEMS4 = NCH * CHE4;
  constexpr int LD4 = (ELEMS4 + 255) / 256;
  constexpr int G = WCH / NCH;
  constexpr int BUFSZ = NCH * IN_H * ROWP;

  extern __shared__ float smem_dyn[];
  float* s_in = smem_dyn;
  float* s_w = smem_dyn + 2 * BUFSZ;

  const int t = threadIdx.x;
  const int tx = t & 15, ty = t >> 4;
  const int ow0 = blockIdx.x * 32, oh0 = blockIdx.y * 16;
  const int HW = Hin * Win;

  int goff4[LD4], soff4[LD4];
#pragma unroll
  for (int i = 0; i < LD4; ++i) {
    int idx = t + i * 256;
    int ch = idx / CHE4;
    int rem = idx - ch * CHE4;
    int r = rem / IN_W4, c4 = rem - r * IN_W4;
    int ih = oh0 * 2 + r, iw = ow0 * 2 + c4 * 4;
    bool slot = (idx < ELEMS4);
    bool ok = slot && ((unsigned)ih < (unsigned)Hin) &&
              ((unsigned)iw < (unsigned)Win);
    goff4[i] = ok ? (ch * HW + ih * Win + iw) : -1;
    soff4[i] = slot ? ((ch * IN_H + r) * ROWP + c4 * 4) : -1;
  }

  unsigned long long acc2[8], cmp2[8];
#pragma unroll
  for (int i = 0; i < 8; ++i) { acc2[i] = 0ull; cmp2[i] = 0ull; }

  for (int chunk = 0; chunk < NCHUNKS; ++chunk) {
    const int c0 = c_begin + chunk * WCH;
    __syncthreads();
#pragma unroll
    for (int i = 0; i < 9; ++i) {
      int idx = t + i * 256;
      int co = idx / (WCH * 9);
      int rem = idx - co * (WCH * 9);
      int ccg = rem / 9, k = rem - ccg * 9;
      s_w[(ccg * 9 + k) * 8 + co] =
          wgt[(size_t)(co0 + co) * CINFULL * 9 + (size_t)(c0 + ccg) * 9 + k];
    }
    {
      const float* inb = in + (size_t)c0 * HW;
      unsigned bufb = (unsigned)__cvta_generic_to_shared(s_in);
#pragma unroll
      for (int i = 0; i < LD4; ++i)
        if (soff4[i] >= 0)
          cp16(bufb + (unsigned)soff4[i] * 4,
               inb + (goff4[i] >= 0 ? goff4[i] : 0), goff4[i] >= 0 ? 16 : 0);
      cp_commit();
    }
    for (int g = 0; g < G; ++g) {
      cp_wait_all();
      __syncthreads();
      if (g + 1 < G) {
        const float* inb = in + (size_t)(c0 + (g + 1) * NCH) * HW;
        unsigned bufb = (unsigned)__cvta_generic_to_shared(
            s_in + ((g + 1) & 1) * BUFSZ);
#pragma unroll
        for (int i = 0; i < LD4; ++i)
          if (soff4[i] >= 0)
            cp16(bufb + (unsigned)soff4[i] * 4,
                 inb + (goff4[i] >= 0 ? goff4[i] : 0), goff4[i] >= 0 ? 16 : 0);
        cp_commit();
      }
      const float* buf = s_in + (g & 1) * BUFSZ;

      unsigned long long wsA[4] = {0ull, 0ull, 0ull, 0ull};
      unsigned long long wsB[4] = {0ull, 0ull, 0ull, 0ull};
#pragma unroll
      for (int chl = 0; chl < NCH; ++chl) {
#pragma unroll
        for (int kh = 0; kh < 3; ++kh) {
          const int rbase = (chl * IN_H + ty * 2 + kh) * ROWP + tx * 4;
          float4 xr = *(const float4*)&buf[rbase];
          float x4v = buf[rbase + 4];
          float x0s[3] = {xr.x, xr.y, xr.z};
          float x1s[3] = {xr.z, xr.w, x4v};
#pragma unroll
          for (int kw = 0; kw < 3; ++kw) {
            unsigned long long x0 = f2_bcast(x0s[kw]);
            unsigned long long x1 = f2_bcast(x1s[kw]);
            const ulonglong2* wp =
                (const ulonglong2*)&s_w[((g * NCH + chl) * 9 + kh * 3 + kw) *
                                        8];
            ulonglong2 wa = wp[0], wb = wp[1];
            wsA[0] = f2_fma(x0, wa.x, wsA[0]);
            wsA[1] = f2_fma(x0, wa.y, wsA[1]);
            wsA[2] = f2_fma(x0, wb.x, wsA[2]);
            wsA[3] = f2_fma(x0, wb.y, wsA[3]);
            wsB[0] = f2_fma(x1, wa.x, wsB[0]);
            wsB[1] = f2_fma(x1, wa.y, wsB[1]);
            wsB[2] = f2_fma(x1, wb.x, wsB[2]);
            wsB[3] = f2_fma(x1, wb.y, wsB[3]);
          }
        }
      }
#pragma unroll
      for (int i = 0; i < 4; ++i) {
        unsigned long long y = f2_fma(cmp2[i], F2_NEG1, wsA[i]);
        unsigned long long tt = f2_add(acc2[i], y);
        unsigned long long t2 = f2_fma(acc2[i], F2_NEG1, tt);
        cmp2[i] = f2_fma(y, F2_NEG1, t2);
        acc2[i] = tt;
      }
#pragma unroll
      for (int i = 0; i < 4; ++i) {
        unsigned long long y = f2_fma(cmp2[4 + i], F2_NEG1, wsB[i]);
        unsigned long long tt = f2_add(acc2[4 + i], y);
        unsigned long long t2 = f2_fma(acc2[4 + i], F2_NEG1, tt);
        cmp2[4 + i] = f2_fma(y, F2_NEG1, t2);
        acc2[4 + i] = tt;
      }
    }
  }

  const int oh = oh0 + ty;
  const int ow = ow0 + tx * 2;
#pragma unroll
  for (int px = 0; px < 2; ++px) {
#pragma unroll
    for (int i = 0; i < 4; ++i) {
      float lo, hi;
      f2_unpack(acc2[px * 4 + i], lo, hi);
      if (FINAL) {
        lo = fmaxf(lo + bias[co0 + 2 * i], 0.f);
        hi = fmaxf(hi + bias[co0 + 2 * i + 1], 0.f);
      }
      out[(size_t)(co0 + 2 * i) * Hout * Wout + (size_t)oh * Wout + ow + px] =
          lo;
      out[(size_t)(co0 + 2 * i + 1) * Hout * Wout + (size_t)oh * Wout + ow +
          px] = hi;
    }
  }
}

static const int CW_SMEM = (2 * 4 * 34 * 68 + 32 * 9 * 8) * 4;  // 83200 B

__global__ void __launch_bounds__(256, 2) k_conv2(const float* w,
                                                  const float* b) {
  conv_wide<64, 2, true>(g_h1, w, b, g_h2, 256, 256, 128, 128, 0,
                         blockIdx.z * 8);
}
__global__ void __launch_bounds__(256, 2) k_conv3(const float* w,
                                                  const float* b) {
  conv_wide<128, 4, true>(g_h2, w, b, g_h3, 128, 128, 64, 64, 0,
                          blockIdx.z * 8);
}
__global__ void __launch_bounds__(256, 2) k_ex(const float* w) {
  const int split = blockIdx.z >> 5;
  const int co0 = (blockIdx.z & 31) * 8;
  conv_wide<256, 2, false>(g_h3, w, nullptr,
                           g_expart + (size_t)split * 256 * 32 * 32, 64, 64,
                           32, 32, split * 64, co0);
}
__global__ void k_combex(const float* __restrict__ b) {
  const int i4 = (blockIdx.x * 256 + threadIdx.x) * 4;
  const int co = i4 >> 10;
  const double bv = (double)b[co];
  float4 p0 = *(const float4*)&g_expart[i4];
  float4 p1 = *(const float4*)&g_expart[262144 + i4];
  float4 p2 = *(const float4*)&g_expart[2 * 262144 + i4];
  float4 p3 = *(const float4*)&g_expart[3 * 262144 + i4];
  float4 o;
  o.x = fmaxf((float)((((double)p0.x + (double)p1.x) + (double)p2.x) +
                      (double)p3.x + bv), 0.f);
  o.y = fmaxf((float)((((double)p0.y + (double)p1.y) + (double)p2.y) +
                      (double)p3.y + bv), 0.f);
  o.z = fmaxf((float)((((double)p0.z + (double)p1.z) + (double)p2.z) +
                      (double)p3.z + bv), 0.f);
  o.w = fmaxf((float)((((double)p0.w + (double)p1.w) + (double)p2.w) +
                      (double)p3.w + bv), 0.f);
  *(float4*)&g_h4[i4] = o;
}

// ---------------- head convs (unchanged, proven) ----------------
__global__ void __launch_bounds__(256) k_head(const float* __restrict__ reg_w,
                                              const float* __restrict__ cls_w) {
  constexpr int IN_T = 34, ROWP = 35, NCH = 4;
  constexpr int ELEMS = NCH * IN_T * IN_T;
  constexpr int LD = (ELEMS + 255) / 256;
  const int split = blockIdx.x, co = blockIdx.y;
  const float* w = (co < 4) ? (reg_w + (size_t)co * 256 * 9)
                            : (cls_w + (size_t)(co - 4) * 256 * 9);
  __shared__ float s_in[NCH * IN_T * ROWP];
  __shared__ float s_w[32 * 9];
  const int t = threadIdx.x;

  int goff[LD], soff[LD];
#pragma unroll
  for (int i = 0; i < LD; ++i) {
    int idx = t + i * 256;
    int ch = idx / (IN_T * IN_T);
    int rem = idx - ch * (IN_T * IN_T);
    int r = rem / IN_T, c = rem - r * IN_T;
    int ih = r - 1, iw = c - 1;
    bool ok = (idx < ELEMS) && ((unsigned)ih < 32u) && ((unsigned)iw < 32u);
    goff[i] = ok ? (ch * 1024 + ih * 32 + iw) : -1;
    soff[i] = (ch * IN_T + r) * ROWP + c;
  }
  for (int idx = t; idx < 32 * 9; idx += 256)
    s_w[idx] = w[(size_t)(split * 32 + idx / 9) * 9 + (idx % 9)];

  float acc[4] = {0.f, 0.f, 0.f, 0.f};
  float cmp[4] = {0.f, 0.f, 0.f, 0.f};

  float rbuf[LD];
  {
    const float* inb = g_h4 + (size_t)split * 32 * 1024;
#pragma unroll
    for (int i = 0; i < LD; ++i) rbuf[i] = (goff[i] >= 0) ? inb[goff[i]] : 0.f;
  }
  for (int g = 0; g < 8; ++g) {
    __syncthreads();
#pragma unroll
    for (int i = 0; i < LD; ++i)
      if (t + i * 256 < ELEMS) s_in[soff[i]] = rbuf[i];
    if (g + 1 < 8) {
      const float* inb = g_h4 + (size_t)(split * 32 + (g + 1) * NCH) * 1024;
#pragma unroll
      for (int i = 0; i < LD; ++i)
        rbuf[i] = (goff[i] >= 0) ? inb[goff[i]] : 0.f;
    }
    __syncthreads();

#pragma unroll
    for (int cc = 0; cc < NCH; ++cc) {
      float wr[9];
#pragma unroll
      for (int k = 0; k < 9; ++k) wr[k] = s_w[(g * NCH + cc) * 9 + k];
#pragma unroll
      for (int px = 0; px < 4; ++px) {
        int p = t + px * 256;
        int oh = p >> 5, ow = p & 31;
        float a = 0.f;
#pragma unroll
        for (int kh = 0; kh < 3; ++kh)
#pragma unroll
          for (int kw = 0; kw < 3; ++kw)
            a = fmaf(s_in[(cc * IN_T + oh + kh) * ROWP + ow + kw],
                     wr[kh * 3 + kw], a);
        float y = a - cmp[px];
        float tt = acc[px] + y;
        cmp[px] = (tt - acc[px]) - y;
        acc[px] = tt;
      }
    }
  }
#pragma unroll
  for (int px = 0; px < 4; ++px)
    g_part[(size_t)(split * 25 + co) * 1024 + t + px * 256] = acc[px];
}

// ---------------- FUSED prep (fp64 reduce + softmax) + stable bitonic sort ----
__global__ void k_prepsort(const float* __restrict__ reg_b,
                           const float* __restrict__ cls_b) {
  __shared__ float s[1024];
  __shared__ int si[1024];
  const int t = threadIdx.x;  // anchor 0..1023

  // prep (identical math to the proven k_prep)
#pragma unroll
  for (int j = 0; j < 4; ++j) {
    double sum = 0.0;
    for (int sp = 0; sp < 8; ++sp)
      sum += (double)g_part[(size_t)(sp * 25 + j) * 1024 + t];
    g_locs[t * 4 + j] = (float)(sum + (double)reg_b[j]);
  }
  float conf[NCLS];
  for (int c = 0; c < NCLS; ++c) {
    double sum = 0.0;
    for (int sp = 0; sp < 8; ++sp)
      sum += (double)g_part[(size_t)(sp * 25 + 4 + c) * 1024 + t];
    conf[c] = (float)(sum + (double)cls_b[c]);
    g_confs[t * NCLS + c] = conf[c];
  }
  float m = conf[0];
  int lab = 0;
  for (int c = 1; c < NCLS; ++c)
    if (conf[c] > m) { m = conf[c]; lab = c; }
  double esum = 0.0;
  for (int c = 0; c < NCLS; ++c) esum += exp((double)conf[c] - (double)m);
  const float score = (float)(1.0 / esum);
  g_labels[t] = lab;

  // sort (identical to the proven k_sort)
  s[t] = score;
  si[t] = t;
  __syncthreads();
  for (int k = 2; k <= 1024; k <<= 1) {
    for (int j = k >> 1; j > 0; j >>= 1) {
      int ixj = t ^ j;
      if (ixj > t) {
        float sa = s[t], sb = s[ixj];
        int ia = si[t], ib = si[ixj];
        bool aFirst = (sa > sb) || (sa == sb && ia < ib);
        bool dirUp = ((t & k) == 0);
        if (dirUp ? !aFirst : aFirst) {
          s[t] = sb; s[ixj] = sa;
          si[t] = ib; si[ixj] = ia;
        }
      }
      __syncthreads();
    }
  }
  const int idx = si[t];
  g_order[t] = idx;
  g_sscore[t] = s[t];
  g_sbox[t] = make_float4(g_locs[idx * 4 + 0], g_locs[idx * 4 + 1],
                          g_locs[idx * 4 + 2], g_locs[idx * 4 + 3]);
  unsigned vb = __ballot_sync(0xffffffffu, s[t] > 0.04f);
  if ((t & 31) == 0) g_validmask[t >> 5] = vb;
}

// ---------------- IoU: lower triangle only (bits j>=i never consumed) --------
__global__ void k_iou() {
  const int i = blockIdx.x, j = threadIdx.x;
  bool dec = false;
  if (j < i) {
    float4 bi = g_sbox[i];
    float4 bj = g_sbox[j];
    float ai = (bi.z - bi.x) * (bi.w - bi.y);
    float aj = (bj.z - bj.x) * (bj.w - bj.y);
    float ltx = fmaxf(bi.x, bj.x), lty = fmaxf(bi.y, bj.y);
    float rbx = fminf(bi.z, bj.z), rby = fminf(bi.w, bj.w);
    float inter = fmaxf(rbx - ltx, 0.f) * fmaxf(rby - lty, 0.f);
    float uni = ai + aj - inter;
    float iou = inter / (uni + 1e-9f);
    if (fabsf(iou - 0.5f) > 1e-4f) {
      dec = iou > 0.5f;
    } else {  // rare ambiguity: resolve at fp64 (proven fallback)
      double dai =
          ((double)bi.z - (double)bi.x) * ((double)bi.w - (double)bi.y);
      double daj =
          ((double)bj.z - (double)bj.x) * ((double)bj.w - (double)bj.y);
      double dlx = fmax((double)bi.x, (double)bj.x);
      double dly = fmax((double)bi.y, (double)bj.y);
      double drx = fmin((double)bi.z, (double)bj.z);
      double dry = fmin((double)bi.w, (double)bj.w);
      double din = fmax(drx - dlx, 0.0) * fmax(dry - dly, 0.0);
      double dio = din / (dai + daj - din + 1e-9);
      dec = dio > 0.5;
    }
  }
  unsigned m = __ballot_sync(0xffffffffu, dec);
  if ((j & 31) == 0) g_sup[i * 32 + (j >> 5)] = m;
}

// ---------------- greedy NMS (proven) ----------------
__global__ void k_nms() {
  const int lane = threadIdx.x;
  unsigned kw = 0;
  const unsigned validw = g_validmask[lane];
  const int CH = 8;
  unsigned buf[CH], nbuf[CH];
#pragma unroll
  for (int q = 0; q < CH; ++q) buf[q] = g_sup[q * 32 + lane];
  for (int c = 0; c < 1024 / CH; ++c) {
    if (c + 1 < 1024 / CH) {
#pragma unroll
      for (int q = 0; q < CH; ++q)
        nbuf[q] = g_sup[((c + 1) * CH + q) * 32 + lane];
    }
#pragma unroll
    for (int q = 0; q < CH; ++q) {
      int i = c * CH + q;
      bool sup = __any_sync(0xffffffffu, (buf[q] & kw) != 0u);
      if (!sup && lane == (i >> 5)) {
        if ((validw >> (i & 31)) & 1u) kw |= (1u << (i & 31));
      }
    }
#pragma unroll
    for (int q = 0; q < CH; ++q) buf[q] = nbuf[q];
  }
  g_keepmask[lane] = kw;
}

// ---------------- masked gather to output (proven) ----------------
__global__ void k_out(float* __restrict__ out) {
  const int p = blockIdx.x * 256 + threadIdx.x;
  const bool keep = (g_keepmask[p >> 5] >> (p & 31)) & 1u;
  const int idx = g_order[p];
  float4 b = g_sbox[p];
  out[p * 4 + 0] = keep ? b.x : -1.0f;
  out[p * 4 + 1] = keep ? b.y : -1.0f;
  out[p * 4 + 2] = keep ? b.z : -1.0f;
  out[p * 4 + 3] = keep ? b.w : -1.0f;
  out[4096 + p] = keep ? (float)g_labels[idx] : 0.0f;
  out[5120 + p] = keep ? g_sscore[p] : -1.0f;
  for (int c = 0; c < NCLS; ++c)
    out[6144 + p * NCLS + c] = keep ? g_confs[idx * NCLS + c] : -1.0f;
}

// ---------------- launch ----------------
extern "C" void kernel_launch(void* const* d_in, const int* in_sizes, int n_in,
                              void* d_out, int out_size) {
  const float* x = (const float*)d_in[0];
  const float* bb_w1 = (const float*)d_in[1];
  const float* bb_b1 = (const float*)d_in[2];
  const float* bb_w2 = (const float*)d_in[3];
  const float* bb_b2 = (const float*)d_in[4];
  const float* bb_w3 = (const float*)d_in[5];
  const float* bb_b3 = (const float*)d_in[6];
  const float* ex_w = (const float*)d_in[7];
  const float* ex_b = (const float*)d_in[8];
  const float* reg_w = (const float*)d_in[9];
  const float* reg_b = (const float*)d_in[10];
  const float* cls_w = (const float*)d_in[11];
  const float* cls_b = (const float*)d_in[12];

  cudaFuncSetAttribute(k_conv2, cudaFuncAttributeMaxDynamicSharedMemorySize,
                       CW_SMEM);
  cudaFuncSetAttribute(k_conv3, cudaFuncAttributeMaxDynamicSharedMemorySize,
                       CW_SMEM);
  cudaFuncSetAttribute(k_ex, cudaFuncAttributeMaxDynamicSharedMemorySize,
                       CW_SMEM);

  // only batch element 7 affects the output
  const float* x7 = x + (size_t)7 * 3 * 512 * 512;

  k_conv1<<<dim3(8, 16, 8), 256>>>(x7, bb_w1, bb_b1);
  k_conv2<<<dim3(4, 8, 16), 256, CW_SMEM>>>(bb_w2, bb_b2);
  k_conv3<<<dim3(2, 4, 32), 256, CW_SMEM>>>(bb_w3, bb_b3);
  k_ex<<<dim3(1, 2, 128), 256, CW_SMEM>>>(ex_w);
  k_combex<<<256, 256>>>(ex_b);
  k_head<<<dim3(8, 25), 256>>>(reg_w, cls_w);
  k_prepsort<<<1, 1024>>>(reg_b, cls_b);
  k_iou<<<1024, 1024>>>();
  k_nms<<<1, 32>>>();
  k_out<<<4, 256>>>((float*)d_out);
}

// round 16
// speedup vs baseline: 1.4595x; 1.4595x over previous
#include <cuda_runtime.h>
#include <math.h>

#define NCLS 21

// ---------------- f32x2 packed helpers ----------------
__device__ __forceinline__ unsigned long long f2_fma(unsigned long long a,
                                                     unsigned long long b,
                                                     unsigned long long c) {
  unsigned long long d;
  asm("fma.rn.f32x2 %0, %1, %2, %3;" : "=l"(d) : "l"(a), "l"(b), "l"(c));
  return d;
}
__device__ __forceinline__ unsigned long long f2_add(unsigned long long a,
                                                     unsigned long long b) {
  unsigned long long d;
  asm("add.rn.f32x2 %0, %1, %2;" : "=l"(d) : "l"(a), "l"(b));
  return d;
}
__device__ __forceinline__ unsigned long long f2_bcast(float x) {
  unsigned long long d;
  asm("mov.b64 %0, {%1, %1};" : "=l"(d) : "f"(x));
  return d;
}
__device__ __forceinline__ void f2_unpack(unsigned long long v, float& lo,
                                          float& hi) {
  asm("mov.b64 {%0, %1}, %2;" : "=f"(lo), "=f"(hi) : "l"(v));
}
#define F2_NEG1 0xBF800000BF800000ULL  // (-1.0f, -1.0f)

// ---------------- cp.async helpers ----------------
__device__ __forceinline__ void cp16(unsigned dst, const void* src,
                                     int srcsize) {
  asm volatile("cp.async.cg.shared.global [%0], [%1], 16, %2;" ::"r"(dst),
               "l"(src), "r"(srcsize));
}
__device__ __forceinline__ void cp_commit() {
  asm volatile("cp.async.commit_group;");
}
__device__ __forceinline__ void cp_wait_all() {
  asm volatile("cp.async.wait_group 0;");
}

// ---------------- scratch ----------------
__device__ float g_h1[64 * 256 * 256];
__device__ float g_h2[128 * 128 * 128];
__device__ float g_h3[256 * 64 * 64];
__device__ float g_h4[256 * 32 * 32];
__device__ float g_expart[4 * 256 * 32 * 32];
__device__ float g_part[8 * 25 * 1024];
__device__ float g_locs[1024 * 4];
__device__ float g_confs[1024 * NCLS];
__device__ float g_scores[1024];
__device__ int g_labels[1024];
__device__ int g_order[1024];
__device__ float4 g_sbox[1024];
__device__ float g_sscore[1024];
__device__ unsigned g_validmask[32];
__device__ unsigned g_sup[1024 * 32];
__device__ unsigned g_keepmask[32];

// ================= conv1 (R11-proven, unchanged) ==============================
__global__ void __launch_bounds__(256) k_conv1(const float* __restrict__ x,
                                               const float* __restrict__ w,
                                               const float* __restrict__ b) {
  constexpr int IN_H = 34, ROWP = 68, IN_W4 = 17;
  constexpr int CHE4 = IN_H * IN_W4;
  constexpr int ELEMS4 = 3 * CHE4;
  constexpr int LD4 = 7;
  __shared__ __align__(16) float s_in[3 * IN_H * ROWP];
  __shared__ __align__(16) float s_w[3 * 9 * 8];

  const int t = threadIdx.x;
  const int tx = t & 15, ty = t >> 4;
  const int ow0 = blockIdx.x * 32, oh0 = blockIdx.y * 16;
  const int co0 = blockIdx.z * 8;

  if (t < 216) {
    int co = t / 27, rem = t - co * 27;
    s_w[rem * 8 + co] = w[(size_t)(co0 + co) * 27 + rem];
  }
#pragma unroll
  for (int i = 0; i < LD4; ++i) {
    int idx = t + i * 256;
    if (idx < ELEMS4) {
      int ch = idx / CHE4, rem = idx - ch * CHE4;
      int r = rem / IN_W4, c4 = rem - r * IN_W4;
      int ih = oh0 * 2 + r, iw = ow0 * 2 + c4 * 4;
      float4 v = make_float4(0.f, 0.f, 0.f, 0.f);
      if (ih < 512 && iw < 512)
        v = *(const float4*)(x + (size_t)ch * 512 * 512 + ih * 512 + iw);
      *(float4*)&s_in[(ch * IN_H + r) * ROWP + c4 * 4] = v;
    }
  }
  __syncthreads();

  unsigned long long acc2[8], cmp2[8];
#pragma unroll
  for (int i = 0; i < 8; ++i) { acc2[i] = 0ull; cmp2[i] = 0ull; }

#pragma unroll
  for (int ch = 0; ch < 3; ++ch) {
    unsigned long long wsA[4] = {0ull, 0ull, 0ull, 0ull};
    unsigned long long wsB[4] = {0ull, 0ull, 0ull, 0ull};
#pragma unroll
    for (int kh = 0; kh < 3; ++kh) {
      const int rbase = (ch * IN_H + ty * 2 + kh) * ROWP + tx * 4;
      float4 xr = *(const float4*)&s_in[rbase];
      float x4v = s_in[rbase + 4];
      float x0s[3] = {xr.x, xr.y, xr.z};
      float x1s[3] = {xr.z, xr.w, x4v};
#pragma unroll
      for (int kw = 0; kw < 3; ++kw) {
        unsigned long long x0 = f2_bcast(x0s[kw]);
        unsigned long long x1 = f2_bcast(x1s[kw]);
        const ulonglong2* wp = (const ulonglong2*)&s_w[(ch * 9 + kh * 3 + kw) * 8];
        ulonglong2 wa = wp[0], wb = wp[1];
        wsA[0] = f2_fma(x0, wa.x, wsA[0]);
        wsA[1] = f2_fma(x0, wa.y, wsA[1]);
        wsA[2] = f2_fma(x0, wb.x, wsA[2]);
        wsA[3] = f2_fma(x0, wb.y, wsA[3]);
        wsB[0] = f2_fma(x1, wa.x, wsB[0]);
        wsB[1] = f2_fma(x1, wa.y, wsB[1]);
        wsB[2] = f2_fma(x1, wb.x, wsB[2]);
        wsB[3] = f2_fma(x1, wb.y, wsB[3]);
      }
    }
#pragma unroll
    for (int i = 0; i < 4; ++i) {
      unsigned long long y = f2_fma(cmp2[i], F2_NEG1, wsA[i]);
      unsigned long long tt = f2_add(acc2[i], y);
      unsigned long long t2 = f2_fma(acc2[i], F2_NEG1, tt);
      cmp2[i] = f2_fma(y, F2_NEG1, t2);
      acc2[i] = tt;
    }
#pragma unroll
    for (int i = 0; i < 4; ++i) {
      unsigned long long y = f2_fma(cmp2[4 + i], F2_NEG1, wsB[i]);
      unsigned long long tt = f2_add(acc2[4 + i], y);
      unsigned long long t2 = f2_fma(acc2[4 + i], F2_NEG1, tt);
      cmp2[4 + i] = f2_fma(y, F2_NEG1, t2);
      acc2[4 + i] = tt;
    }
  }

  const int oh = oh0 + ty;
  const int ow = ow0 + tx * 2;
#pragma unroll
  for (int px = 0; px < 2; ++px) {
#pragma unroll
    for (int i = 0; i < 4; ++i) {
      float lo, hi;
      f2_unpack(acc2[px * 4 + i], lo, hi);
      lo = fmaxf(lo + b[co0 + 2 * i], 0.f);
      hi = fmaxf(hi + b[co0 + 2 * i + 1], 0.f);
      g_h1[(size_t)(co0 + 2 * i) * 65536 + (size_t)oh * 256 + ow + px] = lo;
      g_h1[(size_t)(co0 + 2 * i + 1) * 65536 + (size_t)oh * 256 + ow + px] = hi;
    }
  }
}

// ============= wide conv (exact R13-proven version) ==========================
template <int CINFULL, int NCHUNKS, bool FINAL>
__device__ __forceinline__ void conv_wide(const float* __restrict__ in,
                                          const float* __restrict__ wgt,
                                          const float* __restrict__ bias,
                                          float* __restrict__ out, int Hin,
                                          int Win, int Hout, int Wout,
                                          int c_begin, int co0) {
  constexpr int WCH = 32, NCH = 4;
  constexpr int IN_H = 34, ROWP = 68;
  constexpr int IN_W4 = 17;
  constexpr int CHE4 = IN_H * IN_W4;
  constexpr int ELEMS4 = NCH * CHE4;
  constexpr int LD4 = (ELEMS4 + 255) / 256;
  constexpr int G = WCH / NCH;
  constexpr int BUFSZ = NCH * IN_H * ROWP;

  extern __shared__ float smem_dyn[];
  float* s_in = smem_dyn;
  float* s_w = smem_dyn + 2 * BUFSZ;

  const int t = threadIdx.x;
  const int tx = t & 15, ty = t >> 4;
  const int ow0 = blockIdx.x * 32, oh0 = blockIdx.y * 16;
  const int HW = Hin * Win;

  int goff4[LD4], soff4[LD4];
#pragma unroll
  for (int i = 0; i < LD4; ++i) {
    int idx = t + i * 256;
    int ch = idx / CHE4;
    int rem = idx - ch * CHE4;
    int r = rem / IN_W4, c4 = rem - r * IN_W4;
    int ih = oh0 * 2 + r, iw = ow0 * 2 + c4 * 4;
    bool slot = (idx < ELEMS4);
    bool ok = slot && ((unsigned)ih < (unsigned)Hin) &&
              ((unsigned)iw < (unsigned)Win);
    goff4[i] = ok ? (ch * HW + ih * Win + iw) : -1;
    soff4[i] = slot ? ((ch * IN_H + r) * ROWP + c4 * 4) : -1;
  }

  unsigned long long acc2[8], cmp2[8];
#pragma unroll
  for (int i = 0; i < 8; ++i) { acc2[i] = 0ull; cmp2[i] = 0ull; }

  for (int chunk = 0; chunk < NCHUNKS; ++chunk) {
    const int c0 = c_begin + chunk * WCH;
    __syncthreads();
#pragma unroll
    for (int i = 0; i < 9; ++i) {
      int idx = t + i * 256;
      int co = idx / (WCH * 9);
      int rem = idx - co * (WCH * 9);
      int ccg = rem / 9, k = rem - ccg * 9;
      s_w[(ccg * 9 + k) * 8 + co] =
          wgt[(size_t)(co0 + co) * CINFULL * 9 + (size_t)(c0 + ccg) * 9 + k];
    }
    {
      const float* inb = in + (size_t)c0 * HW;
      unsigned bufb = (unsigned)__cvta_generic_to_shared(s_in);
#pragma unroll
      for (int i = 0; i < LD4; ++i)
        if (soff4[i] >= 0)
          cp16(bufb + (unsigned)soff4[i] * 4,
               inb + (goff4[i] >= 0 ? goff4[i] : 0), goff4[i] >= 0 ? 16 : 0);
      cp_commit();
    }
    for (int g = 0; g < G; ++g) {
      cp_wait_all();
      __syncthreads();
      if (g + 1 < G) {
        const float* inb = in + (size_t)(c0 + (g + 1) * NCH) * HW;
        unsigned bufb = (unsigned)__cvta_generic_to_shared(
            s_in + ((g + 1) & 1) * BUFSZ);
#pragma unroll
        for (int i = 0; i < LD4; ++i)
          if (soff4[i] >= 0)
            cp16(bufb + (unsigned)soff4[i] * 4,
                 inb + (goff4[i] >= 0 ? goff4[i] : 0), goff4[i] >= 0 ? 16 : 0);
        cp_commit();
      }
      const float* buf = s_in + (g & 1) * BUFSZ;

      unsigned long long wsA[4] = {0ull, 0ull, 0ull, 0ull};
      unsigned long long wsB[4] = {0ull, 0ull, 0ull, 0ull};
#pragma unroll
      for (int chl = 0; chl < NCH; ++chl) {
#pragma unroll
        for (int kh = 0; kh < 3; ++kh) {
          const int rbase = (chl * IN_H + ty * 2 + kh) * ROWP + tx * 4;
          float4 xr = *(const float4*)&buf[rbase];
          float x4v = buf[rbase + 4];
          float x0s[3] = {xr.x, xr.y, xr.z};
          float x1s[3] = {xr.z, xr.w, x4v};
#pragma unroll
          for (int kw = 0; kw < 3; ++kw) {
            unsigned long long x0 = f2_bcast(x0s[kw]);
            unsigned long long x1 = f2_bcast(x1s[kw]);
            const ulonglong2* wp =
                (const ulonglong2*)&s_w[((g * NCH + chl) * 9 + kh * 3 + kw) *
                                        8];
            ulonglong2 wa = wp[0], wb = wp[1];
            wsA[0] = f2_fma(x0, wa.x, wsA[0]);
            wsA[1] = f2_fma(x0, wa.y, wsA[1]);
            wsA[2] = f2_fma(x0, wb.x, wsA[2]);
            wsA[3] = f2_fma(x0, wb.y, wsA[3]);
            wsB[0] = f2_fma(x1, wa.x, wsB[0]);
            wsB[1] = f2_fma(x1, wa.y, wsB[1]);
            wsB[2] = f2_fma(x1, wb.x, wsB[2]);
            wsB[3] = f2_fma(x1, wb.y, wsB[3]);
          }
        }
      }
#pragma unroll
      for (int i = 0; i < 4; ++i) {
        unsigned long long y = f2_fma(cmp2[i], F2_NEG1, wsA[i]);
        unsigned long long tt = f2_add(acc2[i], y);
        unsigned long long t2 = f2_fma(acc2[i], F2_NEG1, tt);
        cmp2[i] = f2_fma(y, F2_NEG1, t2);
        acc2[i] = tt;
      }
#pragma unroll
      for (int i = 0; i < 4; ++i) {
        unsigned long long y = f2_fma(cmp2[4 + i], F2_NEG1, wsB[i]);
        unsigned long long tt = f2_add(acc2[4 + i], y);
        unsigned long long t2 = f2_fma(acc2[4 + i], F2_NEG1, tt);
        cmp2[4 + i] = f2_fma(y, F2_NEG1, t2);
        acc2[4 + i] = tt;
      }
    }
  }

  const int oh = oh0 + ty;
  const int ow = ow0 + tx * 2;
#pragma unroll
  for (int px = 0; px < 2; ++px) {
#pragma unroll
    for (int i = 0; i < 4; ++i) {
      float lo, hi;
      f2_unpack(acc2[px * 4 + i], lo, hi);
      if (FINAL) {
        lo = fmaxf(lo + bias[co0 + 2 * i], 0.f);
        hi = fmaxf(hi + bias[co0 + 2 * i + 1], 0.f);
      }
      out[(size_t)(co0 + 2 * i) * Hout * Wout + (size_t)oh * Wout + ow + px] =
          lo;
      out[(size_t)(co0 + 2 * i + 1) * Hout * Wout + (size_t)oh * Wout + ow +
          px] = hi;
    }
  }
}

static const int CW_SMEM = (2 * 4 * 34 * 68 + 32 * 9 * 8) * 4;  // 83200 B

__global__ void __launch_bounds__(256, 2) k_conv2(const float* w,
                                                  const float* b) {
  conv_wide<64, 2, true>(g_h1, w, b, g_h2, 256, 256, 128, 128, 0,
                         blockIdx.z * 8);
}
__global__ void __launch_bounds__(256, 2) k_conv3(const float* w,
                                                  const float* b) {
  conv_wide<128, 4, true>(g_h2, w, b, g_h3, 128, 128, 64, 64, 0,
                          blockIdx.z * 8);
}
__global__ void __launch_bounds__(256, 2) k_ex(const float* w) {
  const int split = blockIdx.z >> 5;
  const int co0 = (blockIdx.z & 31) * 8;
  conv_wide<256, 2, false>(g_h3, w, nullptr,
                           g_expart + (size_t)split * 256 * 32 * 32, 64, 64,
                           32, 32, split * 64, co0);
}
__global__ void k_combex(const float* __restrict__ b) {
  const int i4 = (blockIdx.x * 256 + threadIdx.x) * 4;
  const int co = i4 >> 10;
  const double bv = (double)b[co];
  float4 p0 = *(const float4*)&g_expart[i4];
  float4 p1 = *(const float4*)&g_expart[262144 + i4];
  float4 p2 = *(const float4*)&g_expart[2 * 262144 + i4];
  float4 p3 = *(const float4*)&g_expart[3 * 262144 + i4];
  float4 o;
  o.x = fmaxf((float)((((double)p0.x + (double)p1.x) + (double)p2.x) +
                      (double)p3.x + bv), 0.f);
  o.y = fmaxf((float)((((double)p0.y + (double)p1.y) + (double)p2.y) +
                      (double)p3.y + bv), 0.f);
  o.z = fmaxf((float)((((double)p0.z + (double)p1.z) + (double)p2.z) +
                      (double)p3.z + bv), 0.f);
  o.w = fmaxf((float)((((double)p0.w + (double)p1.w) + (double)p2.w) +
                      (double)p3.w + bv), 0.f);
  *(float4*)&g_h4[i4] = o;
}

// ---------------- head convs (unchanged, proven) ----------------
__global__ void __launch_bounds__(256) k_head(const float* __restrict__ reg_w,
                                              const float* __restrict__ cls_w) {
  constexpr int IN_T = 34, ROWP = 35, NCH = 4;
  constexpr int ELEMS = NCH * IN_T * IN_T;
  constexpr int LD = (ELEMS + 255) / 256;
  const int split = blockIdx.x, co = blockIdx.y;
  const float* w = (co < 4) ? (reg_w + (size_t)co * 256 * 9)
                            : (cls_w + (size_t)(co - 4) * 256 * 9);
  __shared__ float s_in[NCH * IN_T * ROWP];
  __shared__ float s_w[32 * 9];
  const int t = threadIdx.x;

  int goff[LD], soff[LD];
#pragma unroll
  for (int i = 0; i < LD; ++i) {
    int idx = t + i * 256;
    int ch = idx / (IN_T * IN_T);
    int rem = idx - ch * (IN_T * IN_T);
    int r = rem / IN_T, c = rem - r * IN_T;
    int ih = r - 1, iw = c - 1;
    bool ok = (idx < ELEMS) && ((unsigned)ih < 32u) && ((unsigned)iw < 32u);
    goff[i] = ok ? (ch * 1024 + ih * 32 + iw) : -1;
    soff[i] = (ch * IN_T + r) * ROWP + c;
  }
  for (int idx = t; idx < 32 * 9; idx += 256)
    s_w[idx] = w[(size_t)(split * 32 + idx / 9) * 9 + (idx % 9)];

  float acc[4] = {0.f, 0.f, 0.f, 0.f};
  float cmp[4] = {0.f, 0.f, 0.f, 0.f};

  float rbuf[LD];
  {
    const float* inb = g_h4 + (size_t)split * 32 * 1024;
#pragma unroll
    for (int i = 0; i < LD; ++i) rbuf[i] = (goff[i] >= 0) ? inb[goff[i]] : 0.f;
  }
  for (int g = 0; g < 8; ++g) {
    __syncthreads();
#pragma unroll
    for (int i = 0; i < LD; ++i)
      if (t + i * 256 < ELEMS) s_in[soff[i]] = rbuf[i];
    if (g + 1 < 8) {
      const float* inb = g_h4 + (size_t)(split * 32 + (g + 1) * NCH) * 1024;
#pragma unroll
      for (int i = 0; i < LD; ++i)
        rbuf[i] = (goff[i] >= 0) ? inb[goff[i]] : 0.f;
    }
    __syncthreads();

#pragma unroll
    for (int cc = 0; cc < NCH; ++cc) {
      float wr[9];
#pragma unroll
      for (int k = 0; k < 9; ++k) wr[k] = s_w[(g * NCH + cc) * 9 + k];
#pragma unroll
      for (int px = 0; px < 4; ++px) {
        int p = t + px * 256;
        int oh = p >> 5, ow = p & 31;
        float a = 0.f;
#pragma unroll
        for (int kh = 0; kh < 3; ++kh)
#pragma unroll
          for (int kw = 0; kw < 3; ++kw)
            a = fmaf(s_in[(cc * IN_T + oh + kh) * ROWP + ow + kw],
                     wr[kh * 3 + kw], a);
        float y = a - cmp[px];
        float tt = acc[px] + y;
        cmp[px] = (tt - acc[px]) - y;
        acc[px] = tt;
      }
    }
  }
#pragma unroll
  for (int px = 0; px < 4; ++px)
    g_part[(size_t)(split * 25 + co) * 1024 + t + px * 256] = acc[px];
}

// ---------------- reduce partials + softmax (fp64, 4 blocks — proven) --------
__global__ void k_prep(const float* __restrict__ reg_b,
                       const float* __restrict__ cls_b) {
  const int a = blockIdx.x * 256 + threadIdx.x;
#pragma unroll
  for (int j = 0; j < 4; ++j) {
    double s = 0.0;
    for (int sp = 0; sp < 8; ++sp)
      s += (double)g_part[(size_t)(sp * 25 + j) * 1024 + a];
    g_locs[a * 4 + j] = (float)(s + (double)reg_b[j]);
  }
  float conf[NCLS];
  for (int c = 0; c < NCLS; ++c) {
    double s = 0.0;
    for (int sp = 0; sp < 8; ++sp)
      s += (double)g_part[(size_t)(sp * 25 + 4 + c) * 1024 + a];
    conf[c] = (float)(s + (double)cls_b[c]);
    g_confs[a * NCLS + c] = conf[c];
  }
  float m = conf[0];
  int lab = 0;
  for (int c = 1; c < NCLS; ++c)
    if (conf[c] > m) { m = conf[c]; lab = c; }
  double sum = 0.0;
  for (int c = 0; c < NCLS; ++c) sum += exp((double)conf[c] - (double)m);
  g_scores[a] = (float)(1.0 / sum);
  g_labels[a] = lab;
}

// ---------------- stable bitonic sort (proven) ----------------
__global__ void k_sort() {
  __shared__ float s[1024];
  __shared__ int si[1024];
  const int t = threadIdx.x;
  s[t] = g_scores[t];
  si[t] = t;
  __syncthreads();
  for (int k = 2; k <= 1024; k <<= 1) {
    for (int j = k >> 1; j > 0; j >>= 1) {
      int ixj = t ^ j;
      if (ixj > t) {
        float sa = s[t], sb = s[ixj];
        int ia = si[t], ib = si[ixj];
        bool aFirst = (sa > sb) || (sa == sb && ia < ib);
        bool dirUp = ((t & k) == 0);
        if (dirUp ? !aFirst : aFirst) {
          s[t] = sb; s[ixj] = sa;
          si[t] = ib; si[ixj] = ia;
        }
      }
      __syncthreads();
    }
  }
  const int idx = si[t];
  g_order[t] = idx;
  g_sscore[t] = s[t];
  g_sbox[t] = make_float4(g_locs[idx * 4 + 0], g_locs[idx * 4 + 1],
                          g_locs[idx * 4 + 2], g_locs[idx * 4 + 3]);
  unsigned vb = __ballot_sync(0xffffffffu, s[t] > 0.04f);
  if ((t & 31) == 0) g_validmask[t >> 5] = vb;
}

// ---------------- IoU: lower triangle only (bits j>=i never consumed) --------
__global__ void k_iou() {
  const int i = blockIdx.x, j = threadIdx.x;
  bool dec = false;
  if (j < i) {
    float4 bi = g_sbox[i];
    float4 bj = g_sbox[j];
    float ai = (bi.z - bi.x) * (bi.w - bi.y);
    float aj = (bj.z - bj.x) * (bj.w - bj.y);
    float ltx = fmaxf(bi.x, bj.x), lty = fmaxf(bi.y, bj.y);
    float rbx = fminf(bi.z, bj.z), rby = fminf(bi.w, bj.w);
    float inter = fmaxf(rbx - ltx, 0.f) * fmaxf(rby - lty, 0.f);
    float uni = ai + aj - inter;
    float iou = inter / (uni + 1e-9f);
    if (fabsf(iou - 0.5f) > 1e-4f) {
      dec = iou > 0.5f;
    } else {  // rare ambiguity: resolve at fp64 (proven fallback)
      double dai =
          ((double)bi.z - (double)bi.x) * ((double)bi.w - (double)bi.y);
      double daj =
          ((double)bj.z - (double)bj.x) * ((double)bj.w - (double)bj.y);
      double dlx = fmax((double)bi.x, (double)bj.x);
      double dly = fmax((double)bi.y, (double)bj.y);
      double drx = fmin((double)bi.z, (double)bj.z);
      double dry = fmin((double)bi.w, (double)bj.w);
      double din = fmax(drx - dlx, 0.0) * fmax(dry - dly, 0.0);
      double dio = din / (dai + daj - din + 1e-9);
      dec = dio > 0.5;
    }
  }
  unsigned m = __ballot_sync(0xffffffffu, dec);
  if ((j & 31) == 0) g_sup[i * 32 + (j >> 5)] = m;
}

// ---------------- greedy NMS (proven) ----------------
__global__ void k_nms() {
  const int lane = threadIdx.x;
  unsigned kw = 0;
  const unsigned validw = g_validmask[lane];
  const int CH = 8;
  unsigned buf[CH], nbuf[CH];
#pragma unroll
  for (int q = 0; q < CH; ++q) buf[q] = g_sup[q * 32 + lane];
  for (int c = 0; c < 1024 / CH; ++c) {
    if (c + 1 < 1024 / CH) {
#pragma unroll
      for (int q = 0; q < CH; ++q)
        nbuf[q] = g_sup[((c + 1) * CH + q) * 32 + lane];
    }
#pragma unroll
    for (int q = 0; q < CH; ++q) {
      int i = c * CH + q;
      bool sup = __any_sync(0xffffffffu, (buf[q] & kw) != 0u);
      if (!sup && lane == (i >> 5)) {
        if ((validw >> (i & 31)) & 1u) kw |= (1u << (i & 31));
      }
    }
#pragma unroll
    for (int q = 0; q < CH; ++q) buf[q] = nbuf[q];
  }
  g_keepmask[lane] = kw;
}

// ---------------- masked gather to output (proven) ----------------
__global__ void k_out(float* __restrict__ out) {
  const int p = blockIdx.x * 256 + threadIdx.x;
  const bool keep = (g_keepmask[p >> 5] >> (p & 31)) & 1u;
  const int idx = g_order[p];
  float4 b = g_sbox[p];
  out[p * 4 + 0] = keep ? b.x : -1.0f;
  out[p * 4 + 1] = keep ? b.y : -1.0f;
  out[p * 4 + 2] = keep ? b.z : -1.0f;
  out[p * 4 + 3] = keep ? b.w : -1.0f;
  out[4096 + p] = keep ? (float)g_labels[idx] : 0.0f;
  out[5120 + p] = keep ? g_sscore[p] : -1.0f;
  for (int c = 0; c < NCLS; ++c)
    out[6144 + p * NCLS + c] = keep ? g_confs[idx * NCLS + c] : -1.0f;
}

// ---------------- launch ----------------
extern "C" void kernel_launch(void* const* d_in, const int* in_sizes, int n_in,
                              void* d_out, int out_size) {
  const float* x = (const float*)d_in[0];
  const float* bb_w1 = (const float*)d_in[1];
  const float* bb_b1 = (const float*)d_in[2];
  const float* bb_w2 = (const float*)d_in[3];
  const float* bb_b2 = (const float*)d_in[4];
  const float* bb_w3 = (const float*)d_in[5];
  const float* bb_b3 = (const float*)d_in[6];
  const float* ex_w = (const float*)d_in[7];
  const float* ex_b = (const float*)d_in[8];
  const float* reg_w = (const float*)d_in[9];
  const float* reg_b = (const float*)d_in[10];
  const float* cls_w = (const float*)d_in[11];
  const float* cls_b = (const float*)d_in[12];

  cudaFuncSetAttribute(k_conv2, cudaFuncAttributeMaxDynamicSharedMemorySize,
                       CW_SMEM);
  cudaFuncSetAttribute(k_conv3, cudaFuncAttributeMaxDynamicSharedMemorySize,
                       CW_SMEM);
  cudaFuncSetAttribute(k_ex, cudaFuncAttributeMaxDynamicSharedMemorySize,
                       CW_SMEM);

  // only batch element 7 affects the output
  const float* x7 = x + (size_t)7 * 3 * 512 * 512;

  k_conv1<<<dim3(8, 16, 8), 256>>>(x7, bb_w1, bb_b1);
  k_conv2<<<dim3(4, 8, 16), 256, CW_SMEM>>>(bb_w2, bb_b2);
  k_conv3<<<dim3(2, 4, 32), 256, CW_SMEM>>>(bb_w3, bb_b3);
  k_ex<<<dim3(1, 2, 128), 256, CW_SMEM>>>(ex_w);
  k_combex<<<256, 256>>>(ex_b);
  k_head<<<dim3(8, 25), 256>>>(reg_w, cls_w);
  k_prep<<<4, 256>>>(reg_b, cls_b);
  k_sort<<<1, 1024>>>();
  k_iou<<<1024, 1024>>>();
  k_nms<<<1, 32>>>();
  k_out<<<4, 256>>>((float*)d_out);
}